// round 1
// baseline (speedup 1.0000x reference)
#include <cuda_runtime.h>
#include <math.h>

#define SUB_NO 20
#define T_NO   201
#define E_NO   2000
#define I_NO   500
#define NSYN   2500     // E_NO + I_NO
#define T_DATA 20000
#define NCH    60       // 3 variants * 20 subs
#define NC     20       // GEMM k-chunk (divides 500, multiple of 4)
#define CTT    512      // conv t-tile

// output layout (floats): V_hard[20000] V_soft[20000] V_zb[20000]
// theta[50000] hard[50000] soft[50000] zb[50000]
#define OFF_THETA 60000
#define OFF_HARD  110000
#define OFF_SOFT  160000
#define OFF_ZB    210000

// scratch
__device__ float g_in[2][NCH][T_DATA];    // [e/i][channel][t] pre-conv synaptic drive
__device__ float g_syn[NCH][T_DATA];      // post-conv syn_in
__device__ float g_kern[SUB_NO][2][T_NO]; // synaptic kernels

// ---------------------------------------------------------------- zero scratch
__global__ void zero_kernel() {
    const size_t n = (size_t)2 * NCH * T_DATA;
    float* p = &g_in[0][0][0];
    for (size_t i = blockIdx.x * (size_t)blockDim.x + threadIdx.x; i < n;
         i += (size_t)gridDim.x * blockDim.x)
        p[i] = 0.f;
}

// ------------------------------------------------- per-synapse-column prep
__global__ void prep_cols(const float* __restrict__ u, const float* __restrict__ v,
                          const float* __restrict__ clog, float* __restrict__ out) {
    int n = blockIdx.x * blockDim.x + threadIdx.x;
    if (n >= NSYN) return;

    float cl[SUB_NO];
    float m = -1e30f;
#pragma unroll
    for (int s = 0; s < SUB_NO; s++) {
        cl[s] = clog[s * NSYN + n];
        m = fmaxf(m, cl[s]);
    }
    float th[SUB_NO];
    float sum = 0.f;
#pragma unroll
    for (int s = 0; s < SUB_NO; s++) { th[s] = expf(cl[s] - m); sum += th[s]; }
    float inv = 1.f / sum;

    float rz[SUB_NO];
    int k = 0;
    float best = -1e30f;
#pragma unroll
    for (int s = 0; s < SUB_NO; s++) {
        th[s] *= inv;
        float us = u[s * NSYN + n];
        rz[s] = logf(th[s]) - logf(-logf(us));
        if (rz[s] > best) { best = rz[s]; k = s; }   // first-max wins (strict >)
    }
    float log_vk = logf(v[k * NSYN + n]);

#pragma unroll
    for (int s = 0; s < SUB_NO; s++) {
        float hard = (s == k) ? 1.f : 0.f;
        float lv = logf(v[s * NSYN + n]);
        float z_same = -logf(-lv);
        float z_diff = -logf((-lv) / th[s] - log_vk);
        float zb = (s == k) ? z_same : z_diff;
        float sz  = 1.f / (1.f + expf(-2.f * rz[s])) + 1e-9f;
        float szb = 1.f / (1.f + expf(-2.f * zb)) + 1e-9f;
        out[OFF_THETA + s * NSYN + n] = th[s];
        out[OFF_HARD  + s * NSYN + n] = hard;
        out[OFF_SOFT  + s * NSYN + n] = sz;
        out[OFF_ZB    + s * NSYN + n] = szb;
    }
}

// ------------------------------------------------- synaptic kernel table
__global__ void prep_kern(const float* __restrict__ W_syn, const float* __restrict__ Tau,
                          const float* __restrict__ Delta) {
    int i = blockIdx.x * blockDim.x + threadIdx.x;
    if (i >= SUB_NO * 2 * T_NO) return;
    int tau = i % T_NO;
    int j = (i / T_NO) % 2;
    int s = i / (2 * T_NO);
    float d  = expf(Delta[s * 2 + j]);
    float tt = fmaxf((float)tau - d, 0.f) / expf(Tau[s * 2 + j]);
    g_kern[s][j][tau] = tt * expf(-tt) * W_syn[s * 2 + j];
}

// ------------------------------------------------- skinny GEMM: in[t,o] += S[t,:] . C[o,:]
// grid (157, 5): y<4 -> S_e k-chunk of 500; y==4 -> S_i (500 cols).
// 128 threads: warp w owns o-group [15w,15w+15), lane + 32r -> 4 t rows each.
__global__ void gemm_kernel(const float* __restrict__ Se, const float* __restrict__ Si,
                            const float* __restrict__ out) {
    const int y = blockIdx.y;
    const float* S;
    int ldS, sCol, cCol, dst;
    if (y < 4) { S = Se; ldS = E_NO; sCol = y * 500; cCol = y * 500; dst = 0; }
    else       { S = Si; ldS = I_NO; sCol = 0;       cCol = E_NO;    dst = 1; }
    const float* Cb0 = out + OFF_HARD;
    const float* Cb1 = out + OFF_SOFT;
    const float* Cb2 = out + OFF_ZB;

    const int tid = threadIdx.x;
    const int lane = tid & 31;
    const int w = tid >> 5;
    const int oBase = w * 15;
    const int tBase = blockIdx.x * 128;

    __shared__ float Csm[NC][NCH];

    float acc[4][15];
#pragma unroll
    for (int r = 0; r < 4; r++)
#pragma unroll
        for (int o = 0; o < 15; o++) acc[r][o] = 0.f;

    for (int chunk = 0; chunk < 500; chunk += NC) {
        // cooperative C load: NC*60 floats
        for (int i = tid; i < NC * NCH; i += 128) {
            int nn = i / NCH, oo = i % NCH;
            int var = oo / 20, s = oo % 20;
            const float* cb = (var == 0) ? Cb0 : (var == 1) ? Cb1 : Cb2;
            Csm[nn][oo] = cb[s * NSYN + cCol + chunk + nn];
        }
        __syncthreads();

#pragma unroll
        for (int nq = 0; nq < NC / 4; nq++) {
            float4 sv[4];
#pragma unroll
            for (int r = 0; r < 4; r++) {
                int t = tBase + lane + r * 32;
                sv[r] = (t < T_DATA)
                    ? *(const float4*)(S + (size_t)t * ldS + sCol + chunk + nq * 4)
                    : make_float4(0.f, 0.f, 0.f, 0.f);
            }
#pragma unroll
            for (int kk = 0; kk < 4; kk++) {
                int n = nq * 4 + kk;
                float c[15];
#pragma unroll
                for (int o = 0; o < 15; o++) c[o] = Csm[n][oBase + o];
#pragma unroll
                for (int r = 0; r < 4; r++) {
                    float x = (kk == 0) ? sv[r].x : (kk == 1) ? sv[r].y
                            : (kk == 2) ? sv[r].z : sv[r].w;
#pragma unroll
                    for (int o = 0; o < 15; o++) acc[r][o] = fmaf(x, c[o], acc[r][o]);
                }
            }
        }
        __syncthreads();
    }

#pragma unroll
    for (int r = 0; r < 4; r++) {
        int t = tBase + lane + r * 32;
        if (t < T_DATA) {
#pragma unroll
            for (int o = 0; o < 15; o++)
                atomicAdd(&g_in[dst][oBase + o][t], acc[r][o]);
        }
    }
}

// ------------------------------------------------- 201-tap causal FIR, e+i summed
// grid (ceil(T_DATA/CTT), 60), 128 threads, 4 consecutive outputs/thread w/ register rotation
__global__ void conv_kernel() {
    const int o = blockIdx.y;
    const int s = o % 20;
    const int tBase = blockIdx.x * CTT;
    const int tid = threadIdx.x;

    __shared__ float we[CTT + 201], wi[CTT + 201];
    __shared__ float ke[T_NO], ki[T_NO];

    for (int i = tid; i < CTT + 201; i += 128) {
        int gt = tBase - 201 + i;
        bool ok = (gt >= 0) && (gt < T_DATA);
        we[i] = ok ? g_in[0][o][gt] : 0.f;
        wi[i] = ok ? g_in[1][o][gt] : 0.f;
    }
    for (int i = tid; i < T_NO; i += 128) {
        ke[i] = g_kern[s][0][i];
        ki[i] = g_kern[s][1][i];
    }
    __syncthreads();

    const int t0 = tid * 4;   // local output base
    float a0 = 0.f, a1 = 0.f, a2 = 0.f, a3 = 0.f;
    float xe0 = we[201 + t0], xe1 = we[201 + t0 + 1], xe2 = we[201 + t0 + 2], xe3 = we[201 + t0 + 3];
    float xi0 = wi[201 + t0], xi1 = wi[201 + t0 + 1], xi2 = wi[201 + t0 + 2], xi3 = wi[201 + t0 + 3];

#pragma unroll 4
    for (int tau = 0; tau < T_NO; tau++) {
        float fe = ke[tau], fi = ki[tau];
        a0 = fmaf(xe0, fe, fmaf(xi0, fi, a0));
        a1 = fmaf(xe1, fe, fmaf(xi1, fi, a1));
        a2 = fmaf(xe2, fe, fmaf(xi2, fi, a2));
        a3 = fmaf(xe3, fe, fmaf(xi3, fi, a3));
        xe3 = xe2; xe2 = xe1; xe1 = xe0;
        xi3 = xi2; xi2 = xi1; xi1 = xi0;
        int idx = 201 + t0 - (tau + 1);   // >= t0 >= 0 always
        xe0 = we[idx];
        xi0 = wi[idx];
    }

    int t = tBase + t0;
    if (t     < T_DATA) g_syn[o][t]     = a0;
    if (t + 1 < T_DATA) g_syn[o][t + 1] = a1;
    if (t + 2 < T_DATA) g_syn[o][t + 2] = a2;
    if (t + 3 < T_DATA) g_syn[o][t + 3] = a3;
}

// ------------------------------------------------- dendritic tree + tanh
__global__ void tree_kernel(const float* __restrict__ W_sub, const float* __restrict__ V_o,
                            float* __restrict__ outp) {
    int t = blockIdx.x * blockDim.x + threadIdx.x;
    int var = blockIdx.y;
    if (t >= T_DATA) return;

    float ws[SUB_NO];
#pragma unroll
    for (int s = 0; s < SUB_NO; s++) ws[s] = W_sub[s];

    float so[SUB_NO];
#pragma unroll
    for (int si = SUB_NO - 1; si >= 0; si--) {
        float x = g_syn[var * 20 + si][t];
        float leaf = 0.f;
        if (2 * si + 1 < SUB_NO) leaf += so[2 * si + 1] * ws[2 * si + 1];
        if (2 * si + 2 < SUB_NO) leaf += so[2 * si + 2] * ws[2 * si + 2];
        so[si] = tanhf(x + leaf);
    }
    outp[var * T_DATA + t] = so[0] * ws[0] + V_o[0];
}

// ----------------------------------------------------------------------------
extern "C" void kernel_launch(void* const* d_in, const int* in_sizes, int n_in,
                              void* d_out, int out_size) {
    const float* Se    = (const float*)d_in[0];   // S_e  [20000,2000]
    const float* Si    = (const float*)d_in[1];   // S_i  [20000,500]
    const float* u     = (const float*)d_in[2];   // [20,2500]
    const float* v     = (const float*)d_in[3];   // [20,2500]
    const float* Wsyn  = (const float*)d_in[4];   // [20,2]
    const float* Tau   = (const float*)d_in[5];   // [20,2]
    const float* Delta = (const float*)d_in[6];   // [20,2]
    const float* Wsub  = (const float*)d_in[7];   // [20]
    const float* Vo    = (const float*)d_in[8];   // [1]
    // d_in[9] = Theta (unused by reference math)
    const float* Clog  = (const float*)d_in[10];  // [20,2500]
    float* out = (float*)d_out;

    zero_kernel<<<512, 256>>>();
    prep_cols<<<(NSYN + 127) / 128, 128>>>(u, v, Clog, out);
    prep_kern<<<(SUB_NO * 2 * T_NO + 255) / 256, 256>>>(Wsyn, Tau, Delta);
    gemm_kernel<<<dim3((T_DATA + 127) / 128, 5), 128>>>(Se, Si, out);
    conv_kernel<<<dim3((T_DATA + CTT - 1) / CTT, NCH), 128>>>();
    tree_kernel<<<dim3((T_DATA + 255) / 256, 3), 256>>>(Wsub, Vo, out);
}

// round 2
// speedup vs baseline: 1.2440x; 1.2440x over previous
#include <cuda_runtime.h>
#include <math.h>

#define SUB_NO 20
#define T_NO   201
#define E_NO   2000
#define I_NO   500
#define NSYN   2500     // E_NO + I_NO
#define T_DATA 20000
#define NCH    60       // 3 variants * 20 subs
#define NC     20       // GEMM k-chunk (divides 500, multiple of 4)
#define CTT    512      // conv t-tile

// output layout (floats): V_hard[20000] V_soft[20000] V_zb[20000]
// theta[50000] hard[50000] soft[50000] zb[50000]
#define OFF_THETA 60000
#define OFF_HARD  110000
#define OFF_SOFT  160000
#define OFF_ZB    210000

// scratch
__device__ float g_in[2][NCH][T_DATA];    // [e/i][channel][t] pre-conv synaptic drive
__device__ float g_syn[NCH][T_DATA];      // post-conv syn_in
__device__ float g_kern[SUB_NO][2][T_NO]; // synaptic kernels

// ---------------------------------------------------------------- zero scratch
__global__ void zero_kernel() {
    const size_t n = (size_t)2 * NCH * T_DATA;
    float* p = &g_in[0][0][0];
    for (size_t i = blockIdx.x * (size_t)blockDim.x + threadIdx.x; i < n;
         i += (size_t)gridDim.x * blockDim.x)
        p[i] = 0.f;
}

// ------------------------------------------------- per-synapse-column prep
__global__ void prep_cols(const float* __restrict__ u, const float* __restrict__ v,
                          const float* __restrict__ clog, float* __restrict__ out) {
    int n = blockIdx.x * blockDim.x + threadIdx.x;
    if (n >= NSYN) return;

    float cl[SUB_NO];
    float m = -1e30f;
#pragma unroll
    for (int s = 0; s < SUB_NO; s++) {
        cl[s] = clog[s * NSYN + n];
        m = fmaxf(m, cl[s]);
    }
    float th[SUB_NO];
    float sum = 0.f;
#pragma unroll
    for (int s = 0; s < SUB_NO; s++) { th[s] = expf(cl[s] - m); sum += th[s]; }
    float inv = 1.f / sum;

    float rz[SUB_NO];
    int k = 0;
    float best = -1e30f;
#pragma unroll
    for (int s = 0; s < SUB_NO; s++) {
        th[s] *= inv;
        float us = u[s * NSYN + n];
        rz[s] = logf(th[s]) - logf(-logf(us));
        if (rz[s] > best) { best = rz[s]; k = s; }   // first-max wins (strict >)
    }
    float log_vk = logf(v[k * NSYN + n]);

#pragma unroll
    for (int s = 0; s < SUB_NO; s++) {
        float hard = (s == k) ? 1.f : 0.f;
        float lv = logf(v[s * NSYN + n]);
        float z_same = -logf(-lv);
        float z_diff = -logf((-lv) / th[s] - log_vk);
        float zb = (s == k) ? z_same : z_diff;
        float sz  = 1.f / (1.f + expf(-2.f * rz[s])) + 1e-9f;
        float szb = 1.f / (1.f + expf(-2.f * zb)) + 1e-9f;
        out[OFF_THETA + s * NSYN + n] = th[s];
        out[OFF_HARD  + s * NSYN + n] = hard;
        out[OFF_SOFT  + s * NSYN + n] = sz;
        out[OFF_ZB    + s * NSYN + n] = szb;
    }
}

// ------------------------------------------------- synaptic kernel table
__global__ void prep_kern(const float* __restrict__ W_syn, const float* __restrict__ Tau,
                          const float* __restrict__ Delta) {
    int i = blockIdx.x * blockDim.x + threadIdx.x;
    if (i >= SUB_NO * 2 * T_NO) return;
    int tau = i % T_NO;
    int j = (i / T_NO) % 2;
    int s = i / (2 * T_NO);
    float d  = expf(Delta[s * 2 + j]);
    float tt = fmaxf((float)tau - d, 0.f) / expf(Tau[s * 2 + j]);
    g_kern[s][j][tau] = tt * expf(-tt) * W_syn[s * 2 + j];
}

// ------------------------------------------------- skinny GEMM: in[t,o] += S[t,:] . C[o,:]
// grid (157, 5): y<4 -> S_e k-chunk of 500; y==4 -> S_i (500 cols).
// 128 threads: warp w owns o-group [15w,15w+15), lane + 32r -> 4 t rows each.
// S tile staged in smem with coalesced float4 global loads; smem reads are
// stride-21 (conflict-free) scalars; C reads are warp-broadcast.
__global__ void __launch_bounds__(128, 4)
gemm_kernel(const float* __restrict__ Se, const float* __restrict__ Si,
            const float* __restrict__ out) {
    const int y = blockIdx.y;
    const float* S;
    int ldS, sCol, cCol, dst;
    if (y < 4) { S = Se; ldS = E_NO; sCol = y * 500; cCol = y * 500; dst = 0; }
    else       { S = Si; ldS = I_NO; sCol = 0;       cCol = E_NO;    dst = 1; }
    const float* Cb0 = out + OFF_HARD;
    const float* Cb1 = out + OFF_SOFT;
    const float* Cb2 = out + OFF_ZB;

    const int tid = threadIdx.x;
    const int lane = tid & 31;
    const int w = tid >> 5;
    const int oBase = w * 15;
    const int tBase = blockIdx.x * 128;

    __shared__ float Ssm[128][NC + 1];   // pad -> stride 21, conflict-free lane reads
    __shared__ float Csm[NC][NCH];

    float acc[4][15];
#pragma unroll
    for (int r = 0; r < 4; r++)
#pragma unroll
        for (int o = 0; o < 15; o++) acc[r][o] = 0.f;

    for (int chunk = 0; chunk < 500; chunk += NC) {
        // cooperative C load: NC*60 floats
        for (int i = tid; i < NC * NCH; i += 128) {
            int nn = i / NCH, oo = i % NCH;
            int var = oo / 20, s = oo % 20;
            const float* cb = (var == 0) ? Cb0 : (var == 1) ? Cb1 : Cb2;
            Csm[nn][oo] = cb[s * NSYN + cCol + chunk + nn];
        }
        // cooperative S tile load: 128 rows x NC cols, float4-coalesced.
        // (sCol+chunk) is a multiple of 20 floats = 80B -> 16B aligned.
#pragma unroll
        for (int i = tid; i < 128 * (NC / 4); i += 128) {
            int r = i / (NC / 4), c4 = (i % (NC / 4)) * 4;
            int t = tBase + r;
            float4 val = make_float4(0.f, 0.f, 0.f, 0.f);
            if (t < T_DATA)
                val = *(const float4*)(S + (size_t)t * ldS + sCol + chunk + c4);
            Ssm[r][c4]     = val.x;
            Ssm[r][c4 + 1] = val.y;
            Ssm[r][c4 + 2] = val.z;
            Ssm[r][c4 + 3] = val.w;
        }
        __syncthreads();

#pragma unroll
        for (int k = 0; k < NC; k++) {
            float sv0 = Ssm[lane     ][k];
            float sv1 = Ssm[lane + 32][k];
            float sv2 = Ssm[lane + 64][k];
            float sv3 = Ssm[lane + 96][k];
            float c[15];
#pragma unroll
            for (int o = 0; o < 15; o++) c[o] = Csm[k][oBase + o];
#pragma unroll
            for (int o = 0; o < 15; o++) {
                acc[0][o] = fmaf(sv0, c[o], acc[0][o]);
                acc[1][o] = fmaf(sv1, c[o], acc[1][o]);
                acc[2][o] = fmaf(sv2, c[o], acc[2][o]);
                acc[3][o] = fmaf(sv3, c[o], acc[3][o]);
            }
        }
        __syncthreads();
    }

#pragma unroll
    for (int r = 0; r < 4; r++) {
        int t = tBase + lane + r * 32;
        if (t < T_DATA) {
#pragma unroll
            for (int o = 0; o < 15; o++)
                atomicAdd(&g_in[dst][oBase + o][t], acc[r][o]);
        }
    }
}

// ------------------------------------------------- 201-tap causal FIR, e+i summed
// grid (ceil(T_DATA/CTT), 60), 128 threads, 4 consecutive outputs/thread w/ register rotation
__global__ void conv_kernel() {
    const int o = blockIdx.y;
    const int s = o % 20;
    const int tBase = blockIdx.x * CTT;
    const int tid = threadIdx.x;

    __shared__ float we[CTT + 201], wi[CTT + 201];
    __shared__ float ke[T_NO], ki[T_NO];

    for (int i = tid; i < CTT + 201; i += 128) {
        int gt = tBase - 201 + i;
        bool ok = (gt >= 0) && (gt < T_DATA);
        we[i] = ok ? g_in[0][o][gt] : 0.f;
        wi[i] = ok ? g_in[1][o][gt] : 0.f;
    }
    for (int i = tid; i < T_NO; i += 128) {
        ke[i] = g_kern[s][0][i];
        ki[i] = g_kern[s][1][i];
    }
    __syncthreads();

    const int t0 = tid * 4;   // local output base
    float a0 = 0.f, a1 = 0.f, a2 = 0.f, a3 = 0.f;
    float xe0 = we[201 + t0], xe1 = we[201 + t0 + 1], xe2 = we[201 + t0 + 2], xe3 = we[201 + t0 + 3];
    float xi0 = wi[201 + t0], xi1 = wi[201 + t0 + 1], xi2 = wi[201 + t0 + 2], xi3 = wi[201 + t0 + 3];

#pragma unroll 4
    for (int tau = 0; tau < T_NO; tau++) {
        float fe = ke[tau], fi = ki[tau];
        a0 = fmaf(xe0, fe, fmaf(xi0, fi, a0));
        a1 = fmaf(xe1, fe, fmaf(xi1, fi, a1));
        a2 = fmaf(xe2, fe, fmaf(xi2, fi, a2));
        a3 = fmaf(xe3, fe, fmaf(xi3, fi, a3));
        xe3 = xe2; xe2 = xe1; xe1 = xe0;
        xi3 = xi2; xi2 = xi1; xi1 = xi0;
        int idx = 201 + t0 - (tau + 1);   // >= t0 >= 0 always
        xe0 = we[idx];
        xi0 = wi[idx];
    }

    int t = tBase + t0;
    if (t     < T_DATA) g_syn[o][t]     = a0;
    if (t + 1 < T_DATA) g_syn[o][t + 1] = a1;
    if (t + 2 < T_DATA) g_syn[o][t + 2] = a2;
    if (t + 3 < T_DATA) g_syn[o][t + 3] = a3;
}

// ------------------------------------------------- dendritic tree + tanh
__global__ void tree_kernel(const float* __restrict__ W_sub, const float* __restrict__ V_o,
                            float* __restrict__ outp) {
    int t = blockIdx.x * blockDim.x + threadIdx.x;
    int var = blockIdx.y;
    if (t >= T_DATA) return;

    float ws[SUB_NO];
#pragma unroll
    for (int s = 0; s < SUB_NO; s++) ws[s] = W_sub[s];

    float so[SUB_NO];
#pragma unroll
    for (int si = SUB_NO - 1; si >= 0; si--) {
        float x = g_syn[var * 20 + si][t];
        float leaf = 0.f;
        if (2 * si + 1 < SUB_NO) leaf += so[2 * si + 1] * ws[2 * si + 1];
        if (2 * si + 2 < SUB_NO) leaf += so[2 * si + 2] * ws[2 * si + 2];
        so[si] = tanhf(x + leaf);
    }
    outp[var * T_DATA + t] = so[0] * ws[0] + V_o[0];
}

// ----------------------------------------------------------------------------
extern "C" void kernel_launch(void* const* d_in, const int* in_sizes, int n_in,
                              void* d_out, int out_size) {
    const float* Se    = (const float*)d_in[0];   // S_e  [20000,2000]
    const float* Si    = (const float*)d_in[1];   // S_i  [20000,500]
    const float* u     = (const float*)d_in[2];   // [20,2500]
    const float* v     = (const float*)d_in[3];   // [20,2500]
    const float* Wsyn  = (const float*)d_in[4];   // [20,2]
    const float* Tau   = (const float*)d_in[5];   // [20,2]
    const float* Delta = (const float*)d_in[6];   // [20,2]
    const float* Wsub  = (const float*)d_in[7];   // [20]
    const float* Vo    = (const float*)d_in[8];   // [1]
    // d_in[9] = Theta (unused by reference math)
    const float* Clog  = (const float*)d_in[10];  // [20,2500]
    float* out = (float*)d_out;

    zero_kernel<<<512, 256>>>();
    prep_cols<<<(NSYN + 127) / 128, 128>>>(u, v, Clog, out);
    prep_kern<<<(SUB_NO * 2 * T_NO + 255) / 256, 256>>>(Wsyn, Tau, Delta);
    gemm_kernel<<<dim3((T_DATA + 127) / 128, 5), 128>>>(Se, Si, out);
    conv_kernel<<<dim3((T_DATA + CTT - 1) / CTT, NCH), 128>>>();
    tree_kernel<<<dim3((T_DATA + 255) / 256, 3), 256>>>(Wsub, Vo, out);
}

// round 8
// speedup vs baseline: 1.7155x; 1.3790x over previous
#include <cuda_runtime.h>
#include <math.h>
#include <stdint.h>

#define SUB_NO 20
#define T_NO   201
#define E_NO   2000
#define I_NO   500
#define NSYN   2500
#define T_DATA 20000
#define NCH    60
#define CTT    512

#define RANGE_SLOTS 512            // 500 valid k padded to 512 (16 chunks of 32)
#define KSLOTS      (5 * RANGE_SLOTS)

// output layout (floats)
#define OFF_THETA 60000
#define OFF_HARD  110000
#define OFF_SOFT  160000
#define OFF_ZB    210000

// scratch
__device__ float g_in[2][NCH][T_DATA];
__device__ float g_syn[NCH][T_DATA];
__device__ float g_kern[SUB_NO][2][T_NO];
__device__ __align__(16) float g_B[64][KSLOTS];   // padded B: [o(60)+pad4][range*512+j]

// ---------------------------------------------------------------- zero scratch
__global__ void zero_kernel() {
    const size_t n = (size_t)2 * NCH * T_DATA;
    float* p = &g_in[0][0][0];
    for (size_t i = blockIdx.x * (size_t)blockDim.x + threadIdx.x; i < n;
         i += (size_t)gridDim.x * blockDim.x)
        p[i] = 0.f;
}

// ------------------------------------------------- per-synapse-column prep
__global__ void prep_cols(const float* __restrict__ u, const float* __restrict__ v,
                          const float* __restrict__ clog, float* __restrict__ out) {
    int n = blockIdx.x * blockDim.x + threadIdx.x;
    if (n >= NSYN) return;

    float cl[SUB_NO];
    float m = -1e30f;
#pragma unroll
    for (int s = 0; s < SUB_NO; s++) {
        cl[s] = clog[s * NSYN + n];
        m = fmaxf(m, cl[s]);
    }
    float th[SUB_NO];
    float sum = 0.f;
#pragma unroll
    for (int s = 0; s < SUB_NO; s++) { th[s] = expf(cl[s] - m); sum += th[s]; }
    float inv = 1.f / sum;

    float rz[SUB_NO];
    int k = 0;
    float best = -1e30f;
#pragma unroll
    for (int s = 0; s < SUB_NO; s++) {
        th[s] *= inv;
        float us = u[s * NSYN + n];
        rz[s] = logf(th[s]) - logf(-logf(us));
        if (rz[s] > best) { best = rz[s]; k = s; }
    }
    float log_vk = logf(v[k * NSYN + n]);

#pragma unroll
    for (int s = 0; s < SUB_NO; s++) {
        float hard = (s == k) ? 1.f : 0.f;
        float lv = logf(v[s * NSYN + n]);
        float z_same = -logf(-lv);
        float z_diff = -logf((-lv) / th[s] - log_vk);
        float zb = (s == k) ? z_same : z_diff;
        float sz  = 1.f / (1.f + expf(-2.f * rz[s])) + 1e-9f;
        float szb = 1.f / (1.f + expf(-2.f * zb)) + 1e-9f;
        out[OFF_THETA + s * NSYN + n] = th[s];
        out[OFF_HARD  + s * NSYN + n] = hard;
        out[OFF_SOFT  + s * NSYN + n] = sz;
        out[OFF_ZB    + s * NSYN + n] = szb;
    }
}

// ------------------------------------------------- synaptic kernel table
__global__ void prep_kern(const float* __restrict__ W_syn, const float* __restrict__ Tau,
                          const float* __restrict__ Delta) {
    int i = blockIdx.x * blockDim.x + threadIdx.x;
    if (i >= SUB_NO * 2 * T_NO) return;
    int tau = i % T_NO;
    int j = (i / T_NO) % 2;
    int s = i / (2 * T_NO);
    float d  = expf(Delta[s * 2 + j]);
    float tt = fmaxf((float)tau - d, 0.f) / expf(Tau[s * 2 + j]);
    g_kern[s][j][tau] = tt * expf(-tt) * W_syn[s * 2 + j];
}

// ------------------------------------------------- stage padded B (64 x 2560)
// slot layout: range r in 0..4 occupies [r*512, r*512+512); j<500 valid.
// ranges 0..3 -> C columns r*500+j (E part), range 4 -> C columns 2000+j (I part).
__global__ void fill_B(const float* __restrict__ out) {
    int idx = blockIdx.x * blockDim.x + threadIdx.x;
    if (idx >= 64 * KSLOTS) return;
    int o = idx / KSLOTS, slot = idx % KSLOTS;
    int r = slot / RANGE_SLOTS, j = slot % RANGE_SLOTS;
    float val = 0.f;
    if (o < 60 && j < 500) {
        int var = o / 20, s = o % 20;
        const float* cb = out + ((var == 0) ? OFF_HARD : (var == 1) ? OFF_SOFT : OFF_ZB)
                          + s * NSYN;
        val = (r < 4) ? cb[r * 500 + j] : cb[E_NO + j];
    }
    g_B[o][slot] = val;
}

// ------------------------------------------------- tf32 mma.sync GEMM
// grid (157, 5), 128 threads. Block computes D[128 t][64 o] over its 500-k range,
// atomicAdd into g_in[dst]. Warp w owns rows [32w, 32w+32) (2 m16 tiles x 8 n8 tiles).
__global__ void __launch_bounds__(128)
gemm_mma(const float* __restrict__ Se, const float* __restrict__ Si) {
    __shared__ float As[128][33];
    __shared__ float Bs[64][33];

    const int y = blockIdx.y;
    const float* S;
    int ld, kbase, dst;
    if (y < 4) { S = Se; ld = E_NO; kbase = y * 500; dst = 0; }
    else       { S = Si; ld = I_NO; kbase = 0;       dst = 1; }

    const int tid  = threadIdx.x;
    const int lane = tid & 31;
    const int wid  = tid >> 5;
    const int g    = lane >> 2;      // groupID
    const int tg   = lane & 3;       // threadID in group
    const int tBase = blockIdx.x * 128;

    float acc[2][8][4];
#pragma unroll
    for (int mt = 0; mt < 2; mt++)
#pragma unroll
        for (int nt = 0; nt < 8; nt++)
#pragma unroll
            for (int q = 0; q < 4; q++) acc[mt][nt][q] = 0.f;

    for (int chunk = 0; chunk < 16; chunk++) {
        const int j0 = chunk * 32;
        // stage A: 128 rows x 32 k-cols, float4-coalesced, zero-padded
#pragma unroll
        for (int it = 0; it < 8; it++) {
            int idx = tid + it * 128;
            int r = idx >> 3, c4 = (idx & 7) * 4;
            int t = tBase + r, j = j0 + c4;
            float4 v = make_float4(0.f, 0.f, 0.f, 0.f);
            if (t < T_DATA && j < 500)          // j % 4 == 0 and 500 % 4 == 0 -> j+3 valid
                v = *(const float4*)(S + (size_t)t * ld + kbase + j);
            As[r][c4] = v.x; As[r][c4 + 1] = v.y; As[r][c4 + 2] = v.z; As[r][c4 + 3] = v.w;
        }
        // stage B: 64 rows x 32 k-cols from pre-padded g_B
#pragma unroll
        for (int it = 0; it < 4; it++) {
            int idx = tid + it * 128;
            int r = idx >> 3, c4 = (idx & 7) * 4;
            float4 v = *(const float4*)&g_B[r][y * RANGE_SLOTS + j0 + c4];
            Bs[r][c4] = v.x; Bs[r][c4 + 1] = v.y; Bs[r][c4 + 2] = v.z; Bs[r][c4 + 3] = v.w;
        }
        __syncthreads();

#pragma unroll
        for (int k8 = 0; k8 < 4; k8++) {
            const int kk = k8 * 8;
            uint32_t a[2][4];
#pragma unroll
            for (int mt = 0; mt < 2; mt++) {
                int r0 = wid * 32 + mt * 16;
                a[mt][0] = __float_as_uint(As[r0 + g    ][kk + tg    ]);
                a[mt][1] = __float_as_uint(As[r0 + g + 8][kk + tg    ]);
                a[mt][2] = __float_as_uint(As[r0 + g    ][kk + tg + 4]);
                a[mt][3] = __float_as_uint(As[r0 + g + 8][kk + tg + 4]);
            }
            uint32_t b[8][2];
#pragma unroll
            for (int nt = 0; nt < 8; nt++) {
                b[nt][0] = __float_as_uint(Bs[nt * 8 + g][kk + tg    ]);
                b[nt][1] = __float_as_uint(Bs[nt * 8 + g][kk + tg + 4]);
            }
#pragma unroll
            for (int mt = 0; mt < 2; mt++)
#pragma unroll
                for (int nt = 0; nt < 8; nt++) {
                    asm volatile(
                        "mma.sync.aligned.m16n8k8.row.col.f32.tf32.tf32.f32 "
                        "{%0,%1,%2,%3}, {%4,%5,%6,%7}, {%8,%9}, {%0,%1,%2,%3};"
                        : "+f"(acc[mt][nt][0]), "+f"(acc[mt][nt][1]),
                          "+f"(acc[mt][nt][2]), "+f"(acc[mt][nt][3])
                        : "r"(a[mt][0]), "r"(a[mt][1]), "r"(a[mt][2]), "r"(a[mt][3]),
                          "r"(b[nt][0]), "r"(b[nt][1]));
                }
        }
        __syncthreads();
    }

    // epilogue: c0 -> (row, 2*tg), c1 -> (row, 2*tg+1), c2/c3 -> row+8
#pragma unroll
    for (int mt = 0; mt < 2; mt++) {
        int t0 = tBase + wid * 32 + mt * 16 + g;
#pragma unroll
        for (int nt = 0; nt < 8; nt++) {
            int o0 = nt * 8 + tg * 2;
            if (o0 < 60) {
                if (t0 < T_DATA) {
                    atomicAdd(&g_in[dst][o0    ][t0], acc[mt][nt][0]);
                    atomicAdd(&g_in[dst][o0 + 1][t0], acc[mt][nt][1]);
                }
                if (t0 + 8 < T_DATA) {
                    atomicAdd(&g_in[dst][o0    ][t0 + 8], acc[mt][nt][2]);
                    atomicAdd(&g_in[dst][o0 + 1][t0 + 8], acc[mt][nt][3]);
                }
            }
        }
    }
}

// ------------------------------------------------- 201-tap causal FIR, e+i summed
__global__ void conv_kernel() {
    const int o = blockIdx.y;
    const int s = o % 20;
    const int tBase = blockIdx.x * CTT;
    const int tid = threadIdx.x;

    __shared__ float we[CTT + 201], wi[CTT + 201];
    __shared__ float ke[T_NO], ki[T_NO];

    for (int i = tid; i < CTT + 201; i += 128) {
        int gt = tBase - 201 + i;
        bool ok = (gt >= 0) && (gt < T_DATA);
        we[i] = ok ? g_in[0][o][gt] : 0.f;
        wi[i] = ok ? g_in[1][o][gt] : 0.f;
    }
    for (int i = tid; i < T_NO; i += 128) {
        ke[i] = g_kern[s][0][i];
        ki[i] = g_kern[s][1][i];
    }
    __syncthreads();

    const int t0 = tid * 4;
    float a0 = 0.f, a1 = 0.f, a2 = 0.f, a3 = 0.f;
    float xe0 = we[201 + t0], xe1 = we[201 + t0 + 1], xe2 = we[201 + t0 + 2], xe3 = we[201 + t0 + 3];
    float xi0 = wi[201 + t0], xi1 = wi[201 + t0 + 1], xi2 = wi[201 + t0 + 2], xi3 = wi[201 + t0 + 3];

#pragma unroll 4
    for (int tau = 0; tau < T_NO; tau++) {
        float fe = ke[tau], fi = ki[tau];
        a0 = fmaf(xe0, fe, fmaf(xi0, fi, a0));
        a1 = fmaf(xe1, fe, fmaf(xi1, fi, a1));
        a2 = fmaf(xe2, fe, fmaf(xi2, fi, a2));
        a3 = fmaf(xe3, fe, fmaf(xi3, fi, a3));
        xe3 = xe2; xe2 = xe1; xe1 = xe0;
        xi3 = xi2; xi2 = xi1; xi1 = xi0;
        int idx = 201 + t0 - (tau + 1);
        xe0 = we[idx];
        xi0 = wi[idx];
    }

    int t = tBase + t0;
    if (t     < T_DATA) g_syn[o][t]     = a0;
    if (t + 1 < T_DATA) g_syn[o][t + 1] = a1;
    if (t + 2 < T_DATA) g_syn[o][t + 2] = a2;
    if (t + 3 < T_DATA) g_syn[o][t + 3] = a3;
}

// ------------------------------------------------- dendritic tree + tanh
__global__ void tree_kernel(const float* __restrict__ W_sub, const float* __restrict__ V_o,
                            float* __restrict__ outp) {
    int t = blockIdx.x * blockDim.x + threadIdx.x;
    int var = blockIdx.y;
    if (t >= T_DATA) return;

    float ws[SUB_NO];
#pragma unroll
    for (int s = 0; s < SUB_NO; s++) ws[s] = W_sub[s];

    float so[SUB_NO];
#pragma unroll
    for (int si = SUB_NO - 1; si >= 0; si--) {
        float x = g_syn[var * 20 + si][t];
        float leaf = 0.f;
        if (2 * si + 1 < SUB_NO) leaf += so[2 * si + 1] * ws[2 * si + 1];
        if (2 * si + 2 < SUB_NO) leaf += so[2 * si + 2] * ws[2 * si + 2];
        so[si] = tanhf(x + leaf);
    }
    outp[var * T_DATA + t] = so[0] * ws[0] + V_o[0];
}

// ----------------------------------------------------------------------------
extern "C" void kernel_launch(void* const* d_in, const int* in_sizes, int n_in,
                              void* d_out, int out_size) {
    const float* Se    = (const float*)d_in[0];
    const float* Si    = (const float*)d_in[1];
    const float* u     = (const float*)d_in[2];
    const float* v     = (const float*)d_in[3];
    const float* Wsyn  = (const float*)d_in[4];
    const float* Tau   = (const float*)d_in[5];
    const float* Delta = (const float*)d_in[6];
    const float* Wsub  = (const float*)d_in[7];
    const float* Vo    = (const float*)d_in[8];
    const float* Clog  = (const float*)d_in[10];
    float* out = (float*)d_out;

    zero_kernel<<<512, 256>>>();
    prep_cols<<<(NSYN + 127) / 128, 128>>>(u, v, Clog, out);
    prep_kern<<<(SUB_NO * 2 * T_NO + 255) / 256, 256>>>(Wsyn, Tau, Delta);
    fill_B<<<(64 * KSLOTS + 255) / 256, 256>>>(out);
    gemm_mma<<<dim3((T_DATA + 127) / 128, 5), 128>>>(Se, Si);
    conv_kernel<<<dim3((T_DATA + CTT - 1) / CTT, NCH), 128>>>();
    tree_kernel<<<dim3((T_DATA + 255) / 256, 3), 256>>>(Wsub, Vo, out);
}

// round 9
// speedup vs baseline: 2.5255x; 1.4722x over previous
#include <cuda_runtime.h>
#include <math.h>
#include <stdint.h>

#define SUB_NO 20
#define T_NO   201
#define E_NO   2000
#define I_NO   500
#define NSYN   2500
#define T_DATA 20000
#define NCH    60
#define CTT    512

#define NCHUNK_E 63                 // ceil(2000/32)
#define NCHUNK_I 16                 // ceil(500/32)
#define NCHUNKS  (NCHUNK_E + NCHUNK_I)
#define KSLOTS   (NCHUNKS * 32)     // 2528

// output layout (floats)
#define OFF_THETA 60000
#define OFF_HARD  110000
#define OFF_SOFT  160000
#define OFF_ZB    210000

// scratch
__device__ float g_in[2][NCH][T_DATA];
__device__ float g_syn[NCH][T_DATA];
__device__ float g_kern[SUB_NO][2][T_NO];
__device__ __align__(16) float g_B[64][KSLOTS];   // padded B: chunk*32+j slots

// ------------------------------------------------- per-synapse-column prep
__global__ void prep_cols(const float* __restrict__ u, const float* __restrict__ v,
                          const float* __restrict__ clog, float* __restrict__ out) {
    int n = blockIdx.x * blockDim.x + threadIdx.x;
    if (n >= NSYN) return;

    float cl[SUB_NO];
    float m = -1e30f;
#pragma unroll
    for (int s = 0; s < SUB_NO; s++) {
        cl[s] = clog[s * NSYN + n];
        m = fmaxf(m, cl[s]);
    }
    float th[SUB_NO];
    float sum = 0.f;
#pragma unroll
    for (int s = 0; s < SUB_NO; s++) { th[s] = expf(cl[s] - m); sum += th[s]; }
    float inv = 1.f / sum;

    float rz[SUB_NO];
    int k = 0;
    float best = -1e30f;
#pragma unroll
    for (int s = 0; s < SUB_NO; s++) {
        th[s] *= inv;
        float us = u[s * NSYN + n];
        rz[s] = logf(th[s]) - logf(-logf(us));
        if (rz[s] > best) { best = rz[s]; k = s; }
    }
    float log_vk = logf(v[k * NSYN + n]);

#pragma unroll
    for (int s = 0; s < SUB_NO; s++) {
        float hard = (s == k) ? 1.f : 0.f;
        float lv = logf(v[s * NSYN + n]);
        float z_same = -logf(-lv);
        float z_diff = -logf((-lv) / th[s] - log_vk);
        float zb = (s == k) ? z_same : z_diff;
        float sz  = 1.f / (1.f + expf(-2.f * rz[s])) + 1e-9f;
        float szb = 1.f / (1.f + expf(-2.f * zb)) + 1e-9f;
        out[OFF_THETA + s * NSYN + n] = th[s];
        out[OFF_HARD  + s * NSYN + n] = hard;
        out[OFF_SOFT  + s * NSYN + n] = sz;
        out[OFF_ZB    + s * NSYN + n] = szb;
    }
}

// ------------------------------------------------- synaptic kernel table
__global__ void prep_kern(const float* __restrict__ W_syn, const float* __restrict__ Tau,
                          const float* __restrict__ Delta) {
    int i = blockIdx.x * blockDim.x + threadIdx.x;
    if (i >= SUB_NO * 2 * T_NO) return;
    int tau = i % T_NO;
    int j = (i / T_NO) % 2;
    int s = i / (2 * T_NO);
    float d  = expf(Delta[s * 2 + j]);
    float tt = fmaxf((float)tau - d, 0.f) / expf(Tau[s * 2 + j]);
    g_kern[s][j][tau] = tt * expf(-tt) * W_syn[s * 2 + j];
}

// ------------------------------------------------- stage padded B (64 x 2528)
// chunk < 63 -> E cols chunk*32+j (<2000), chunk >= 63 -> I cols (chunk-63)*32+j (<500)
__global__ void fill_B(const float* __restrict__ out) {
    int idx = blockIdx.x * blockDim.x + threadIdx.x;
    if (idx >= 64 * KSLOTS) return;
    int o = idx / KSLOTS, slot = idx % KSLOTS;
    int chunk = slot >> 5, j = slot & 31;
    float val = 0.f;
    if (o < 60) {
        int var = o / 20, s = o % 20;
        const float* cb = out + ((var == 0) ? OFF_HARD : (var == 1) ? OFF_SOFT : OFF_ZB)
                          + s * NSYN;
        if (chunk < NCHUNK_E) {
            int col = chunk * 32 + j;
            if (col < E_NO) val = cb[col];
        } else {
            int col = (chunk - NCHUNK_E) * 32 + j;
            if (col < I_NO) val = cb[E_NO + col];
        }
    }
    g_B[o][slot] = val;
}

// ------------------------------------------------- helpers
__device__ __forceinline__ uint32_t smem_u32(const void* p) {
    uint32_t r;
    asm("{ .reg .u64 t; cvta.to.shared.u64 t, %1; cvt.u32.u64 %0, t; }" : "=r"(r) : "l"(p));
    return r;
}
__device__ __forceinline__ void ldsm4(uint32_t r[4], uint32_t addr) {
    asm volatile("ldmatrix.sync.aligned.m8n8.x4.shared.b16 {%0,%1,%2,%3}, [%4];"
                 : "=r"(r[0]), "=r"(r[1]), "=r"(r[2]), "=r"(r[3]) : "r"(addr));
}

// ------------------------------------------------- tf32 mma.sync GEMM, full-K per block
// grid 157, block 128. Warp w owns t-rows [tBase+32w, +32). E chunks first
// (acc -> g_in[0]), then I chunks (acc -> g_in[1]). No atomics.
#define APAD 36
__global__ void __launch_bounds__(128, 1)
gemm_mma(const float* __restrict__ Se, const float* __restrict__ Si) {
    __shared__ float As[128][APAD];
    __shared__ float Bs[64][APAD];

    const int tid  = threadIdx.x;
    const int lane = tid & 31;
    const int wid  = tid >> 5;
    const int g    = lane >> 2;
    const int tg   = lane & 3;
    const int tBase = blockIdx.x * 128;

    // ldmatrix lane->address precompute (byte addresses, 16B aligned)
    const int aRow = wid * 32 + (lane & 7) + ((lane >> 3) & 1) * 8;
    const int aCol = (lane >> 4) * 4;
    const uint32_t aAddr0 = smem_u32(&As[aRow][aCol]);
    const uint32_t aAddr1 = aAddr0 + 16 * APAD * 4;
    uint32_t bAddr[4];
#pragma unroll
    for (int p = 0; p < 4; p++) {
        int bRow = (2 * p + (lane >> 4)) * 8 + (lane & 7);
        int bCol = ((lane >> 3) & 1) * 4;
        bAddr[p] = smem_u32(&Bs[bRow][bCol]);
    }
    // staging indices
    const int sr = tid >> 3;              // A row (this thread's first of 8 strided)
    const int sc = (tid & 7) * 4;         // k-col

    float acc[2][8][4];
    float4 va[8], vb[4];

    // LDG one chunk into registers
    auto ldg_chunk = [&](int c) {
        const float* S; int ld, kmax, j0;
        if (c < NCHUNK_E) { S = Se; ld = E_NO; kmax = E_NO; j0 = c * 32; }
        else              { S = Si; ld = I_NO; kmax = I_NO; j0 = (c - NCHUNK_E) * 32; }
        int j = j0 + sc;
#pragma unroll
        for (int it = 0; it < 8; it++) {
            int t = tBase + sr + it * 16;
            va[it] = (t < T_DATA && j < kmax)
                ? *(const float4*)(S + (size_t)t * ld + j)
                : make_float4(0.f, 0.f, 0.f, 0.f);
        }
        int slot = c * 32 + sc;
#pragma unroll
        for (int it = 0; it < 4; it++)
            vb[it] = *(const float4*)&g_B[sr + it * 16][slot];
    };
    auto sts_chunk = [&]() {
#pragma unroll
        for (int it = 0; it < 8; it++)
            *(float4*)&As[sr + it * 16][sc] = va[it];
#pragma unroll
        for (int it = 0; it < 4; it++)
            *(float4*)&Bs[sr + it * 16][sc] = vb[it];
    };
    auto compute_chunk = [&]() {
#pragma unroll
        for (int k8 = 0; k8 < 4; k8++) {
            const uint32_t koff = k8 * 32;   // 8 floats
            uint32_t af[2][4], bf[4][4];
            ldsm4(af[0], aAddr0 + koff);
            ldsm4(af[1], aAddr1 + koff);
#pragma unroll
            for (int p = 0; p < 4; p++) ldsm4(bf[p], bAddr[p] + koff);
#pragma unroll
            for (int mt = 0; mt < 2; mt++)
#pragma unroll
                for (int nt = 0; nt < 8; nt++) {
                    const uint32_t b0 = bf[nt >> 1][(nt & 1) * 2];
                    const uint32_t b1 = bf[nt >> 1][(nt & 1) * 2 + 1];
                    asm volatile(
                        "mma.sync.aligned.m16n8k8.row.col.f32.tf32.tf32.f32 "
                        "{%0,%1,%2,%3}, {%4,%5,%6,%7}, {%8,%9}, {%0,%1,%2,%3};"
                        : "+f"(acc[mt][nt][0]), "+f"(acc[mt][nt][1]),
                          "+f"(acc[mt][nt][2]), "+f"(acc[mt][nt][3])
                        : "r"(af[mt][0]), "r"(af[mt][1]), "r"(af[mt][2]), "r"(af[mt][3]),
                          "r"(b0), "r"(b1));
                }
        }
    };
    auto store_acc = [&](int dst) {
#pragma unroll
        for (int mt = 0; mt < 2; mt++) {
            int t0 = tBase + wid * 32 + mt * 16 + g;
#pragma unroll
            for (int nt = 0; nt < 8; nt++) {
                int o0 = nt * 8 + tg * 2;
                if (o0 < 60) {
                    if (t0 < T_DATA) {
                        g_in[dst][o0    ][t0] = acc[mt][nt][0];
                        g_in[dst][o0 + 1][t0] = acc[mt][nt][1];
                    }
                    if (t0 + 8 < T_DATA) {
                        g_in[dst][o0    ][t0 + 8] = acc[mt][nt][2];
                        g_in[dst][o0 + 1][t0 + 8] = acc[mt][nt][3];
                    }
                }
            }
        }
    };
    auto zero_acc = [&]() {
#pragma unroll
        for (int mt = 0; mt < 2; mt++)
#pragma unroll
            for (int nt = 0; nt < 8; nt++)
#pragma unroll
                for (int q = 0; q < 4; q++) acc[mt][nt][q] = 0.f;
    };

    // ---- E pass ----
    zero_acc();
    ldg_chunk(0);
    for (int c = 0; c < NCHUNK_E; c++) {
        sts_chunk();
        __syncthreads();
        if (c + 1 < NCHUNK_E) ldg_chunk(c + 1);
        compute_chunk();
        __syncthreads();
    }
    store_acc(0);

    // ---- I pass ----
    zero_acc();
    ldg_chunk(NCHUNK_E);
    for (int c = NCHUNK_E; c < NCHUNKS; c++) {
        sts_chunk();
        __syncthreads();
        if (c + 1 < NCHUNKS) ldg_chunk(c + 1);
        compute_chunk();
        __syncthreads();
    }
    store_acc(1);
}

// ------------------------------------------------- 201-tap causal FIR, e+i summed
__global__ void conv_kernel() {
    const int o = blockIdx.y;
    const int s = o % 20;
    const int tBase = blockIdx.x * CTT;
    const int tid = threadIdx.x;

    __shared__ float we[CTT + 201], wi[CTT + 201];
    __shared__ float ke[T_NO], ki[T_NO];

    for (int i = tid; i < CTT + 201; i += 128) {
        int gt = tBase - 201 + i;
        bool ok = (gt >= 0) && (gt < T_DATA);
        we[i] = ok ? g_in[0][o][gt] : 0.f;
        wi[i] = ok ? g_in[1][o][gt] : 0.f;
    }
    for (int i = tid; i < T_NO; i += 128) {
        ke[i] = g_kern[s][0][i];
        ki[i] = g_kern[s][1][i];
    }
    __syncthreads();

    const int t0 = tid * 4;
    float a0 = 0.f, a1 = 0.f, a2 = 0.f, a3 = 0.f;
    float xe0 = we[201 + t0], xe1 = we[201 + t0 + 1], xe2 = we[201 + t0 + 2], xe3 = we[201 + t0 + 3];
    float xi0 = wi[201 + t0], xi1 = wi[201 + t0 + 1], xi2 = wi[201 + t0 + 2], xi3 = wi[201 + t0 + 3];

#pragma unroll 4
    for (int tau = 0; tau < T_NO; tau++) {
        float fe = ke[tau], fi = ki[tau];
        a0 = fmaf(xe0, fe, fmaf(xi0, fi, a0));
        a1 = fmaf(xe1, fe, fmaf(xi1, fi, a1));
        a2 = fmaf(xe2, fe, fmaf(xi2, fi, a2));
        a3 = fmaf(xe3, fe, fmaf(xi3, fi, a3));
        xe3 = xe2; xe2 = xe1; xe1 = xe0;
        xi3 = xi2; xi2 = xi1; xi1 = xi0;
        int idx = 201 + t0 - (tau + 1);
        xe0 = we[idx];
        xi0 = wi[idx];
    }

    int t = tBase + t0;
    if (t     < T_DATA) g_syn[o][t]     = a0;
    if (t + 1 < T_DATA) g_syn[o][t + 1] = a1;
    if (t + 2 < T_DATA) g_syn[o][t + 2] = a2;
    if (t + 3 < T_DATA) g_syn[o][t + 3] = a3;
}

// ------------------------------------------------- dendritic tree + tanh
__global__ void tree_kernel(const float* __restrict__ W_sub, const float* __restrict__ V_o,
                            float* __restrict__ outp) {
    int t = blockIdx.x * blockDim.x + threadIdx.x;
    int var = blockIdx.y;
    if (t >= T_DATA) return;

    float ws[SUB_NO];
#pragma unroll
    for (int s = 0; s < SUB_NO; s++) ws[s] = W_sub[s];

    float so[SUB_NO];
#pragma unroll
    for (int si = SUB_NO - 1; si >= 0; si--) {
        float x = g_syn[var * 20 + si][t];
        float leaf = 0.f;
        if (2 * si + 1 < SUB_NO) leaf += so[2 * si + 1] * ws[2 * si + 1];
        if (2 * si + 2 < SUB_NO) leaf += so[2 * si + 2] * ws[2 * si + 2];
        so[si] = tanhf(x + leaf);
    }
    outp[var * T_DATA + t] = so[0] * ws[0] + V_o[0];
}

// ----------------------------------------------------------------------------
extern "C" void kernel_launch(void* const* d_in, const int* in_sizes, int n_in,
                              void* d_out, int out_size) {
    const float* Se    = (const float*)d_in[0];
    const float* Si    = (const float*)d_in[1];
    const float* u     = (const float*)d_in[2];
    const float* v     = (const float*)d_in[3];
    const float* Wsyn  = (const float*)d_in[4];
    const float* Tau   = (const float*)d_in[5];
    const float* Delta = (const float*)d_in[6];
    const float* Wsub  = (const float*)d_in[7];
    const float* Vo    = (const float*)d_in[8];
    const float* Clog  = (const float*)d_in[10];
    float* out = (float*)d_out;

    prep_cols<<<(NSYN + 127) / 128, 128>>>(u, v, Clog, out);
    prep_kern<<<(SUB_NO * 2 * T_NO + 255) / 256, 256>>>(Wsyn, Tau, Delta);
    fill_B<<<(64 * KSLOTS + 255) / 256, 256>>>(out);
    gemm_mma<<<(T_DATA + 127) / 128, 128>>>(Se, Si);
    conv_kernel<<<dim3((T_DATA + CTT - 1) / CTT, NCH), 128>>>();
    tree_kernel<<<dim3((T_DATA + 255) / 256, 3), 256>>>(Wsub, Vo, out);
}

// round 10
// speedup vs baseline: 2.8414x; 1.1251x over previous
#include <cuda_runtime.h>
#include <math.h>
#include <stdint.h>

#define SUB_NO 20
#define T_NO   201
#define E_NO   2000
#define I_NO   500
#define NSYN   2500
#define T_DATA 20000
#define NCH    60
#define CTT    512

#define NCHUNK_E 63                 // ceil(2000/32)
#define NCHUNK_I 16                 // ceil(500/32)
#define NCHUNKS  (NCHUNK_E + NCHUNK_I)
#define KSLOTS   (NCHUNKS * 32)     // 2528

// output layout (floats)
#define OFF_THETA 60000
#define OFF_HARD  110000
#define OFF_SOFT  160000
#define OFF_ZB    210000

// scratch
__device__ float g_in[2][NCH][T_DATA];
__device__ float g_syn[NCH][T_DATA];
__device__ float g_kern[SUB_NO][2][T_NO];
__device__ __align__(16) float g_B[64][KSLOTS];  // padding slots/rows stay 0 (static init, never written)

// ------------------------------------------------- per-synapse-column prep (warp per column)
// Also writes the padded B operand directly (replaces fill_B).
__global__ void prep_cols(const float* __restrict__ u, const float* __restrict__ v,
                          const float* __restrict__ clog, float* __restrict__ out) {
    const unsigned FULL = 0xFFFFFFFFu;
    int n = (blockIdx.x * blockDim.x + threadIdx.x) >> 5;
    int lane = threadIdx.x & 31;
    if (n >= NSYN) return;
    const bool act = lane < SUB_NO;

    float cl = act ? clog[lane * NSYN + n] : -1e30f;
    float m = cl;
#pragma unroll
    for (int o = 16; o; o >>= 1) m = fmaxf(m, __shfl_xor_sync(FULL, m, o));
    float e = act ? expf(cl - m) : 0.f;
    float sum = e;
#pragma unroll
    for (int o = 16; o; o >>= 1) sum += __shfl_xor_sync(FULL, sum, o);
    float th = e / sum;

    float rz = -1e30f;
    if (act) {
        float us = u[lane * NSYN + n];
        rz = logf(th) - logf(-logf(us));
    }
    float mr = rz;
#pragma unroll
    for (int o = 16; o; o >>= 1) mr = fmaxf(mr, __shfl_xor_sync(FULL, mr, o));
    unsigned msk = __ballot_sync(FULL, rz == mr);
    int k = __ffs(msk) - 1;                     // first max (lowest s)

    float vs = act ? v[lane * NSYN + n] : 0.5f;
    float lv = logf(vs);
    float lvk = __shfl_sync(FULL, lv, k);

    if (act) {
        float hard = (lane == k) ? 1.f : 0.f;
        float z_same = -logf(-lv);
        float z_diff = -logf((-lv) / th - lvk);
        float zb = (lane == k) ? z_same : z_diff;
        float sz  = 1.f / (1.f + expf(-2.f * rz)) + 1e-9f;
        float szb = 1.f / (1.f + expf(-2.f * zb)) + 1e-9f;
        out[OFF_THETA + lane * NSYN + n] = th;
        out[OFF_HARD  + lane * NSYN + n] = hard;
        out[OFF_SOFT  + lane * NSYN + n] = sz;
        out[OFF_ZB    + lane * NSYN + n] = szb;
        int slot = (n < E_NO) ? n : (NCHUNK_E * 32 + (n - E_NO));
        g_B[lane     ][slot] = hard;
        g_B[20 + lane][slot] = sz;
        g_B[40 + lane][slot] = szb;
    }
}

// ------------------------------------------------- synaptic kernel table
__global__ void prep_kern(const float* __restrict__ W_syn, const float* __restrict__ Tau,
                          const float* __restrict__ Delta) {
    int i = blockIdx.x * blockDim.x + threadIdx.x;
    if (i >= SUB_NO * 2 * T_NO) return;
    int tau = i % T_NO;
    int j = (i / T_NO) % 2;
    int s = i / (2 * T_NO);
    float d  = expf(Delta[s * 2 + j]);
    float tt = fmaxf((float)tau - d, 0.f) / expf(Tau[s * 2 + j]);
    g_kern[s][j][tau] = tt * expf(-tt) * W_syn[s * 2 + j];
}

// ------------------------------------------------- helpers
__device__ __forceinline__ uint32_t smem_u32(const void* p) {
    uint32_t r;
    asm("{ .reg .u64 t; cvta.to.shared.u64 t, %1; cvt.u32.u64 %0, t; }" : "=r"(r) : "l"(p));
    return r;
}
__device__ __forceinline__ void ldsm4(uint32_t r[4], uint32_t addr) {
    asm volatile("ldmatrix.sync.aligned.m8n8.x4.shared.b16 {%0,%1,%2,%3}, [%4];"
                 : "=r"(r[0]), "=r"(r[1]), "=r"(r[2]), "=r"(r[3]) : "r"(addr));
}
__device__ __forceinline__ void cpa16(uint32_t dst, const void* src, int sz) {
    asm volatile("cp.async.cg.shared.global [%0], [%1], 16, %2;"
                 :: "r"(dst), "l"(src), "r"(sz));
}

// ------------------------------------------------- tf32 mma.sync GEMM, cp.async 4-stage
// grid 157, 256 threads (8 warps). Warp w owns t-rows [tBase+16w, +16).
// E chunks accumulate -> g_in[0], then I chunks -> g_in[1]. No atomics.
#define APAD   36
#define STAGES 4
#define A_STAGE (128 * APAD)        // floats
#define B_STAGE (64 * APAD)
#define GEMM_SMEM (STAGES * (A_STAGE + B_STAGE) * 4)

__global__ void __launch_bounds__(256, 1)
gemm_mma(const float* __restrict__ Se, const float* __restrict__ Si) {
    extern __shared__ float smem[];
    float* Asm = smem;
    float* Bsm = smem + STAGES * A_STAGE;

    const int tid  = threadIdx.x;
    const int lane = tid & 31;
    const int wid  = tid >> 5;
    const int g    = lane >> 2;
    const int tg   = lane & 3;
    const int tBase = blockIdx.x * 128;

    const uint32_t aBase = smem_u32(Asm);
    const uint32_t bBase = smem_u32(Bsm);

    // ldmatrix lane->address (stage 0)
    const int aRow = wid * 16 + (lane & 7) + ((lane >> 3) & 1) * 8;
    const int aCol = (lane >> 4) * 4;
    const uint32_t aAddr = aBase + (uint32_t)(aRow * APAD + aCol) * 4;
    uint32_t bAddr[4];
#pragma unroll
    for (int p = 0; p < 4; p++) {
        int bRow = (2 * p + (lane >> 4)) * 8 + (lane & 7);
        int bCol = ((lane >> 3) & 1) * 4;
        bAddr[p] = bBase + (uint32_t)(bRow * APAD + bCol) * 4;
    }

    // staging indices: thread -> (row, 4-float col)
    const int sr = tid >> 3;          // 0..31
    const int sc = (tid & 7) * 4;     // 0..28

    float acc[8][4];
#pragma unroll
    for (int nt = 0; nt < 8; nt++)
#pragma unroll
        for (int q = 0; q < 4; q++) acc[nt][q] = 0.f;

    auto issue = [&](int c, int st) {
        const float* S; int ld, kmax, j0;
        if (c < NCHUNK_E) { S = Se; ld = E_NO; kmax = E_NO; j0 = c * 32; }
        else              { S = Si; ld = I_NO; kmax = I_NO; j0 = (c - NCHUNK_E) * 32; }
        int j = j0 + sc;
        bool jok = j < kmax;
        uint32_t adst = aBase + (uint32_t)(st * A_STAGE + sr * APAD + sc) * 4;
#pragma unroll
        for (int it = 0; it < 4; it++) {
            int t = tBase + sr + it * 32;
            bool ok = jok && (t < T_DATA);
            cpa16(adst + it * 32 * APAD * 4,
                  ok ? (const void*)(S + (size_t)t * ld + j) : (const void*)S,
                  ok ? 16 : 0);
        }
        uint32_t bdst = bBase + (uint32_t)(st * B_STAGE + sr * APAD + sc) * 4;
        int slot = c * 32 + sc;
#pragma unroll
        for (int it = 0; it < 2; it++)
            cpa16(bdst + it * 32 * APAD * 4, &g_B[sr + it * 32][slot], 16);
    };

    auto compute = [&](int st) {
        const uint32_t ao = (uint32_t)(st * A_STAGE) * 4;
        const uint32_t bo = (uint32_t)(st * B_STAGE) * 4;
#pragma unroll
        for (int k8 = 0; k8 < 4; k8++) {
            const uint32_t koff = k8 * 32;
            uint32_t af[4], bf[4][4];
            ldsm4(af, aAddr + ao + koff);
#pragma unroll
            for (int p = 0; p < 4; p++) ldsm4(bf[p], bAddr[p] + bo + koff);
#pragma unroll
            for (int nt = 0; nt < 8; nt++) {
                const uint32_t b0 = bf[nt >> 1][(nt & 1) * 2];
                const uint32_t b1 = bf[nt >> 1][(nt & 1) * 2 + 1];
                asm volatile(
                    "mma.sync.aligned.m16n8k8.row.col.f32.tf32.tf32.f32 "
                    "{%0,%1,%2,%3}, {%4,%5,%6,%7}, {%8,%9}, {%0,%1,%2,%3};"
                    : "+f"(acc[nt][0]), "+f"(acc[nt][1]),
                      "+f"(acc[nt][2]), "+f"(acc[nt][3])
                    : "r"(af[0]), "r"(af[1]), "r"(af[2]), "r"(af[3]),
                      "r"(b0), "r"(b1));
            }
        }
    };

    auto store_acc = [&](int dst) {
        int t0 = tBase + wid * 16 + g;
#pragma unroll
        for (int nt = 0; nt < 8; nt++) {
            int o0 = nt * 8 + tg * 2;
            if (o0 < 60) {
                if (t0 < T_DATA) {
                    g_in[dst][o0    ][t0] = acc[nt][0];
                    g_in[dst][o0 + 1][t0] = acc[nt][1];
                }
                if (t0 + 8 < T_DATA) {
                    g_in[dst][o0    ][t0 + 8] = acc[nt][2];
                    g_in[dst][o0 + 1][t0 + 8] = acc[nt][3];
                }
            }
        }
    };

    // prefetch STAGES-1 chunks
#pragma unroll
    for (int p = 0; p < STAGES - 1; p++) {
        issue(p, p);
        asm volatile("cp.async.commit_group;" ::: "memory");
    }

    for (int c = 0; c < NCHUNKS; c++) {
        asm volatile("cp.async.wait_group %0;" :: "n"(STAGES - 2) : "memory");
        __syncthreads();
        int nc = c + STAGES - 1;
        if (nc < NCHUNKS) issue(nc, nc & (STAGES - 1));
        asm volatile("cp.async.commit_group;" ::: "memory");   // uniform group count
        compute(c & (STAGES - 1));
        if (c == NCHUNK_E - 1) {
            store_acc(0);
#pragma unroll
            for (int nt = 0; nt < 8; nt++)
#pragma unroll
                for (int q = 0; q < 4; q++) acc[nt][q] = 0.f;
        }
    }
    store_acc(1);
}

// ------------------------------------------------- causal FIR, e+i summed, truncated taps
__global__ void conv_kernel(const float* __restrict__ Tau, const float* __restrict__ Delta) {
    const int o = blockIdx.y;
    const int s = o % 20;
    const int tBase = blockIdx.x * CTT;
    const int tid = threadIdx.x;

    // effective kernel length: t_tau*e^{-t_tau} < ~5e-11 beyond t_tau = 27
    float de = expf(Delta[s * 2 + 0]), di = expf(Delta[s * 2 + 1]);
    float te = expf(Tau[s * 2 + 0]),   ti = expf(Tau[s * 2 + 1]);
    int L = (int)(fmaxf(de + 27.f * te, di + 27.f * ti)) + 2;
    if (L > T_NO) L = T_NO;

    __shared__ float we[CTT + 201], wi[CTT + 201];
    __shared__ float ke[T_NO], ki[T_NO];

    for (int i = tid; i < CTT + 201; i += 128) {
        int gt = tBase - 201 + i;
        bool ok = (gt >= 0) && (gt < T_DATA);
        we[i] = ok ? g_in[0][o][gt] : 0.f;
        wi[i] = ok ? g_in[1][o][gt] : 0.f;
    }
    for (int i = tid; i < T_NO; i += 128) {
        ke[i] = g_kern[s][0][i];
        ki[i] = g_kern[s][1][i];
    }
    __syncthreads();

    const int t0 = tid * 4;
    float a0 = 0.f, a1 = 0.f, a2 = 0.f, a3 = 0.f;
    float xe0 = we[201 + t0], xe1 = we[201 + t0 + 1], xe2 = we[201 + t0 + 2], xe3 = we[201 + t0 + 3];
    float xi0 = wi[201 + t0], xi1 = wi[201 + t0 + 1], xi2 = wi[201 + t0 + 2], xi3 = wi[201 + t0 + 3];

#pragma unroll 4
    for (int tau = 0; tau < L; tau++) {
        float fe = ke[tau], fi = ki[tau];
        a0 = fmaf(xe0, fe, fmaf(xi0, fi, a0));
        a1 = fmaf(xe1, fe, fmaf(xi1, fi, a1));
        a2 = fmaf(xe2, fe, fmaf(xi2, fi, a2));
        a3 = fmaf(xe3, fe, fmaf(xi3, fi, a3));
        xe3 = xe2; xe2 = xe1; xe1 = xe0;
        xi3 = xi2; xi2 = xi1; xi1 = xi0;
        int idx = 201 + t0 - (tau + 1);
        xe0 = we[idx];
        xi0 = wi[idx];
    }

    int t = tBase + t0;
    if (t     < T_DATA) g_syn[o][t]     = a0;
    if (t + 1 < T_DATA) g_syn[o][t + 1] = a1;
    if (t + 2 < T_DATA) g_syn[o][t + 2] = a2;
    if (t + 3 < T_DATA) g_syn[o][t + 3] = a3;
}

// ------------------------------------------------- dendritic tree + tanh
__global__ void tree_kernel(const float* __restrict__ W_sub, const float* __restrict__ V_o,
                            float* __restrict__ outp) {
    int t = blockIdx.x * blockDim.x + threadIdx.x;
    int var = blockIdx.y;
    if (t >= T_DATA) return;

    float ws[SUB_NO];
#pragma unroll
    for (int s = 0; s < SUB_NO; s++) ws[s] = W_sub[s];

    float so[SUB_NO];
#pragma unroll
    for (int si = SUB_NO - 1; si >= 0; si--) {
        float x = g_syn[var * 20 + si][t];
        float leaf = 0.f;
        if (2 * si + 1 < SUB_NO) leaf += so[2 * si + 1] * ws[2 * si + 1];
        if (2 * si + 2 < SUB_NO) leaf += so[2 * si + 2] * ws[2 * si + 2];
        so[si] = tanhf(x + leaf);
    }
    outp[var * T_DATA + t] = so[0] * ws[0] + V_o[0];
}

// ----------------------------------------------------------------------------
extern "C" void kernel_launch(void* const* d_in, const int* in_sizes, int n_in,
                              void* d_out, int out_size) {
    const float* Se    = (const float*)d_in[0];
    const float* Si    = (const float*)d_in[1];
    const float* u     = (const float*)d_in[2];
    const float* v     = (const float*)d_in[3];
    const float* Wsyn  = (const float*)d_in[4];
    const float* Tau   = (const float*)d_in[5];
    const float* Delta = (const float*)d_in[6];
    const float* Wsub  = (const float*)d_in[7];
    const float* Vo    = (const float*)d_in[8];
    const float* Clog  = (const float*)d_in[10];
    float* out = (float*)d_out;

    cudaFuncSetAttribute(gemm_mma, cudaFuncAttributeMaxDynamicSharedMemorySize, GEMM_SMEM);

    prep_cols<<<(NSYN * 32 + 255) / 256, 256>>>(u, v, Clog, out);
    prep_kern<<<(SUB_NO * 2 * T_NO + 255) / 256, 256>>>(Wsyn, Tau, Delta);
    gemm_mma<<<(T_DATA + 127) / 128, 256, GEMM_SMEM>>>(Se, Si);
    conv_kernel<<<dim3((T_DATA + CTT - 1) / CTT, NCH), 128>>>(Tau, Delta);
    tree_kernel<<<dim3((T_DATA + 255) / 256, 3), 256>>>(Wsub, Vo, out);
}

// round 11
// speedup vs baseline: 2.9615x; 1.0423x over previous
#include <cuda_runtime.h>
#include <math.h>
#include <stdint.h>

#define SUB_NO 20
#define T_NO   201
#define E_NO   2000
#define I_NO   500
#define NSYN   2500
#define T_DATA 20000
#define NCH    60
#define CTT    512
#define OFFS   208                 // window history pad (mult of 4, >= 200+8)

#define NCHUNK_E 63                 // ceil(2000/32)
#define NCHUNK_I 16                 // ceil(500/32)
#define NCHUNKS  (NCHUNK_E + NCHUNK_I)
#define KSLOTS   (NCHUNKS * 32)     // 2528

// output layout (floats)
#define OFF_THETA 60000
#define OFF_HARD  110000
#define OFF_SOFT  160000
#define OFF_ZB    210000

// scratch
__device__ float g_in[2][NCH][T_DATA];
__device__ float g_syn[NCH][T_DATA];
__device__ float g_kern[SUB_NO][2][T_NO];
__device__ __align__(16) float g_B[64][KSLOTS];  // padding slots/rows stay 0 (static init, never written)

// ------------------------------------------------- per-synapse-column prep (warp per column)
__global__ void prep_cols(const float* __restrict__ u, const float* __restrict__ v,
                          const float* __restrict__ clog, float* __restrict__ out) {
    const unsigned FULL = 0xFFFFFFFFu;
    int n = (blockIdx.x * blockDim.x + threadIdx.x) >> 5;
    int lane = threadIdx.x & 31;
    if (n >= NSYN) return;
    const bool act = lane < SUB_NO;

    float cl = act ? clog[lane * NSYN + n] : -1e30f;
    float m = cl;
#pragma unroll
    for (int o = 16; o; o >>= 1) m = fmaxf(m, __shfl_xor_sync(FULL, m, o));
    float e = act ? expf(cl - m) : 0.f;
    float sum = e;
#pragma unroll
    for (int o = 16; o; o >>= 1) sum += __shfl_xor_sync(FULL, sum, o);
    float th = e / sum;

    float rz = -1e30f;
    if (act) {
        float us = u[lane * NSYN + n];
        rz = logf(th) - logf(-logf(us));
    }
    float mr = rz;
#pragma unroll
    for (int o = 16; o; o >>= 1) mr = fmaxf(mr, __shfl_xor_sync(FULL, mr, o));
    unsigned msk = __ballot_sync(FULL, rz == mr);
    int k = __ffs(msk) - 1;                     // first max (lowest s)

    float vs = act ? v[lane * NSYN + n] : 0.5f;
    float lv = logf(vs);
    float lvk = __shfl_sync(FULL, lv, k);

    if (act) {
        float hard = (lane == k) ? 1.f : 0.f;
        float z_same = -logf(-lv);
        float z_diff = -logf((-lv) / th - lvk);
        float zb = (lane == k) ? z_same : z_diff;
        float sz  = 1.f / (1.f + expf(-2.f * rz)) + 1e-9f;
        float szb = 1.f / (1.f + expf(-2.f * zb)) + 1e-9f;
        out[OFF_THETA + lane * NSYN + n] = th;
        out[OFF_HARD  + lane * NSYN + n] = hard;
        out[OFF_SOFT  + lane * NSYN + n] = sz;
        out[OFF_ZB    + lane * NSYN + n] = szb;
        int slot = (n < E_NO) ? n : (NCHUNK_E * 32 + (n - E_NO));
        g_B[lane     ][slot] = hard;
        g_B[20 + lane][slot] = sz;
        g_B[40 + lane][slot] = szb;
    }
}

// ------------------------------------------------- synaptic kernel table
__global__ void prep_kern(const float* __restrict__ W_syn, const float* __restrict__ Tau,
                          const float* __restrict__ Delta) {
    int i = blockIdx.x * blockDim.x + threadIdx.x;
    if (i >= SUB_NO * 2 * T_NO) return;
    int tau = i % T_NO;
    int j = (i / T_NO) % 2;
    int s = i / (2 * T_NO);
    float d  = expf(Delta[s * 2 + j]);
    float tt = fmaxf((float)tau - d, 0.f) / expf(Tau[s * 2 + j]);
    g_kern[s][j][tau] = tt * expf(-tt) * W_syn[s * 2 + j];
}

// ------------------------------------------------- helpers
__device__ __forceinline__ uint32_t smem_u32(const void* p) {
    uint32_t r;
    asm("{ .reg .u64 t; cvta.to.shared.u64 t, %1; cvt.u32.u64 %0, t; }" : "=r"(r) : "l"(p));
    return r;
}
__device__ __forceinline__ void ldsm4(uint32_t r[4], uint32_t addr) {
    asm volatile("ldmatrix.sync.aligned.m8n8.x4.shared.b16 {%0,%1,%2,%3}, [%4];"
                 : "=r"(r[0]), "=r"(r[1]), "=r"(r[2]), "=r"(r[3]) : "r"(addr));
}
__device__ __forceinline__ void cpa16(uint32_t dst, const void* src, int sz) {
    asm volatile("cp.async.cg.shared.global [%0], [%1], 16, %2;"
                 :: "r"(dst), "l"(src), "r"(sz));
}

// ------------------------------------------------- tf32 mma.sync GEMM, cp.async 2-stage
// grid 157, 256 threads (8 warps), 55.3KB smem -> 2 CTAs/SM (no tail wave).
// Warp w owns t-rows [tBase+16w, +16). E chunks -> g_in[0], I chunks -> g_in[1].
#define APAD   36
#define STAGES 2
#define A_STAGE (128 * APAD)        // floats
#define B_STAGE (64 * APAD)
#define GEMM_SMEM (STAGES * (A_STAGE + B_STAGE) * 4)

__global__ void __launch_bounds__(256, 2)
gemm_mma(const float* __restrict__ Se, const float* __restrict__ Si) {
    extern __shared__ float smem[];
    float* Asm = smem;
    float* Bsm = smem + STAGES * A_STAGE;

    const int tid  = threadIdx.x;
    const int lane = tid & 31;
    const int wid  = tid >> 5;
    const int g    = lane >> 2;
    const int tg   = lane & 3;
    const int tBase = blockIdx.x * 128;

    const uint32_t aBase = smem_u32(Asm);
    const uint32_t bBase = smem_u32(Bsm);

    // ldmatrix lane->address (stage 0)
    const int aRow = wid * 16 + (lane & 7) + ((lane >> 3) & 1) * 8;
    const int aCol = (lane >> 4) * 4;
    const uint32_t aAddr = aBase + (uint32_t)(aRow * APAD + aCol) * 4;
    uint32_t bAddr[4];
#pragma unroll
    for (int p = 0; p < 4; p++) {
        int bRow = (2 * p + (lane >> 4)) * 8 + (lane & 7);
        int bCol = ((lane >> 3) & 1) * 4;
        bAddr[p] = bBase + (uint32_t)(bRow * APAD + bCol) * 4;
    }

    // staging indices
    const int sr = tid >> 3;          // 0..31
    const int sc = (tid & 7) * 4;     // 0..28

    float acc[8][4];
#pragma unroll
    for (int nt = 0; nt < 8; nt++)
#pragma unroll
        for (int q = 0; q < 4; q++) acc[nt][q] = 0.f;

    auto issue = [&](int c, int st) {
        const float* S; int ld, kmax, j0;
        if (c < NCHUNK_E) { S = Se; ld = E_NO; kmax = E_NO; j0 = c * 32; }
        else              { S = Si; ld = I_NO; kmax = I_NO; j0 = (c - NCHUNK_E) * 32; }
        int j = j0 + sc;
        bool jok = j < kmax;
        uint32_t adst = aBase + (uint32_t)(st * A_STAGE + sr * APAD + sc) * 4;
#pragma unroll
        for (int it = 0; it < 4; it++) {
            int t = tBase + sr + it * 32;
            bool ok = jok && (t < T_DATA);
            cpa16(adst + it * 32 * APAD * 4,
                  ok ? (const void*)(S + (size_t)t * ld + j) : (const void*)S,
                  ok ? 16 : 0);
        }
        uint32_t bdst = bBase + (uint32_t)(st * B_STAGE + sr * APAD + sc) * 4;
        int slot = c * 32 + sc;
#pragma unroll
        for (int it = 0; it < 2; it++)
            cpa16(bdst + it * 32 * APAD * 4, &g_B[sr + it * 32][slot], 16);
    };

    auto compute = [&](int st) {
        const uint32_t ao = (uint32_t)(st * A_STAGE) * 4;
        const uint32_t bo = (uint32_t)(st * B_STAGE) * 4;
#pragma unroll
        for (int k8 = 0; k8 < 4; k8++) {
            const uint32_t koff = k8 * 32;
            uint32_t af[4], bf[4][4];
            ldsm4(af, aAddr + ao + koff);
#pragma unroll
            for (int p = 0; p < 4; p++) ldsm4(bf[p], bAddr[p] + bo + koff);
#pragma unroll
            for (int nt = 0; nt < 8; nt++) {
                const uint32_t b0 = bf[nt >> 1][(nt & 1) * 2];
                const uint32_t b1 = bf[nt >> 1][(nt & 1) * 2 + 1];
                asm volatile(
                    "mma.sync.aligned.m16n8k8.row.col.f32.tf32.tf32.f32 "
                    "{%0,%1,%2,%3}, {%4,%5,%6,%7}, {%8,%9}, {%0,%1,%2,%3};"
                    : "+f"(acc[nt][0]), "+f"(acc[nt][1]),
                      "+f"(acc[nt][2]), "+f"(acc[nt][3])
                    : "r"(af[0]), "r"(af[1]), "r"(af[2]), "r"(af[3]),
                      "r"(b0), "r"(b1));
            }
        }
    };

    auto store_acc = [&](int dst) {
        int t0 = tBase + wid * 16 + g;
#pragma unroll
        for (int nt = 0; nt < 8; nt++) {
            int o0 = nt * 8 + tg * 2;
            if (o0 < 60) {
                if (t0 < T_DATA) {
                    g_in[dst][o0    ][t0] = acc[nt][0];
                    g_in[dst][o0 + 1][t0] = acc[nt][1];
                }
                if (t0 + 8 < T_DATA) {
                    g_in[dst][o0    ][t0 + 8] = acc[nt][2];
                    g_in[dst][o0 + 1][t0 + 8] = acc[nt][3];
                }
            }
        }
    };

    // double-buffer: prefetch chunk 0
    issue(0, 0);
    asm volatile("cp.async.commit_group;" ::: "memory");

    for (int c = 0; c < NCHUNKS; c++) {
        asm volatile("cp.async.wait_group 0;" ::: "memory");
        __syncthreads();
        if (c + 1 < NCHUNKS) {
            issue(c + 1, (c + 1) & 1);
            asm volatile("cp.async.commit_group;" ::: "memory");
        }
        compute(c & 1);
        if (c == NCHUNK_E - 1) {
            store_acc(0);
#pragma unroll
            for (int nt = 0; nt < 8; nt++)
#pragma unroll
                for (int q = 0; q < 4; q++) acc[nt][q] = 0.f;
        }
    }
    store_acc(1);
}

// ------------------------------------------------- causal FIR: float4 sliding window,
// conflict-free LDS.128, truncated taps. grid (40, 60), 128 threads, 4 outputs/thread.
__global__ void conv_kernel(const float* __restrict__ Tau, const float* __restrict__ Delta) {
    const int o = blockIdx.y;
    const int s = o % 20;
    const int tBase = blockIdx.x * CTT;
    const int tid = threadIdx.x;

    // effective length: t_tau*e^{-t_tau} < ~5e-11 beyond t_tau = 27
    float de = expf(Delta[s * 2 + 0]), di = expf(Delta[s * 2 + 1]);
    float te = expf(Tau[s * 2 + 0]),   ti = expf(Tau[s * 2 + 1]);
    int L = (int)(fmaxf(de + 27.f * te, di + 27.f * ti)) + 2;
    if (L > T_NO) L = T_NO;
    const int L4 = (L + 3) & ~3;     // multiple of 4, <= 204

    __shared__ __align__(16) float we[CTT + OFFS], wi[CTT + OFFS];
    __shared__ __align__(16) float ke[204], ki[204];

    for (int i = tid; i < CTT + OFFS; i += 128) {
        int gt = tBase - OFFS + i;
        bool ok = (gt >= 0) && (gt < T_DATA);
        we[i] = ok ? g_in[0][o][gt] : 0.f;
        wi[i] = ok ? g_in[1][o][gt] : 0.f;
    }
    for (int i = tid; i < 204; i += 128) {
        ke[i] = (i < T_NO) ? g_kern[s][0][i] : 0.f;
        ki[i] = (i < T_NO) ? g_kern[s][1][i] : 0.f;
    }
    __syncthreads();

    const int t0 = tid * 4;
    float a0 = 0.f, a1 = 0.f, a2 = 0.f, a3 = 0.f;

    // window regs: p=0..7 <-> we[OFFS + t0 - tau4 - 4 + p]
    float4 lo_e = *(const float4*)&we[OFFS + t0 - 4];
    float4 hi_e = *(const float4*)&we[OFFS + t0];
    float4 lo_i = *(const float4*)&wi[OFFS + t0 - 4];
    float4 hi_i = *(const float4*)&wi[OFFS + t0];

    for (int tau4 = 0; tau4 < L4; tau4 += 4) {
        float4 kfe = *(const float4*)&ke[tau4];
        float4 kfi = *(const float4*)&ki[tau4];
        // m=0: positions 4..7 = hi
        a0 = fmaf(hi_e.x, kfe.x, fmaf(hi_i.x, kfi.x, a0));
        a1 = fmaf(hi_e.y, kfe.x, fmaf(hi_i.y, kfi.x, a1));
        a2 = fmaf(hi_e.z, kfe.x, fmaf(hi_i.z, kfi.x, a2));
        a3 = fmaf(hi_e.w, kfe.x, fmaf(hi_i.w, kfi.x, a3));
        // m=1: positions 3..6
        a0 = fmaf(lo_e.w, kfe.y, fmaf(lo_i.w, kfi.y, a0));
        a1 = fmaf(hi_e.x, kfe.y, fmaf(hi_i.x, kfi.y, a1));
        a2 = fmaf(hi_e.y, kfe.y, fmaf(hi_i.y, kfi.y, a2));
        a3 = fmaf(hi_e.z, kfe.y, fmaf(hi_i.z, kfi.y, a3));
        // m=2: positions 2..5
        a0 = fmaf(lo_e.z, kfe.z, fmaf(lo_i.z, kfi.z, a0));
        a1 = fmaf(lo_e.w, kfe.z, fmaf(lo_i.w, kfi.z, a1));
        a2 = fmaf(hi_e.x, kfe.z, fmaf(hi_i.x, kfi.z, a2));
        a3 = fmaf(hi_e.y, kfe.z, fmaf(hi_i.y, kfi.z, a3));
        // m=3: positions 1..4
        a0 = fmaf(lo_e.y, kfe.w, fmaf(lo_i.y, kfi.w, a0));
        a1 = fmaf(lo_e.z, kfe.w, fmaf(lo_i.z, kfi.w, a1));
        a2 = fmaf(lo_e.w, kfe.w, fmaf(lo_i.w, kfi.w, a2));
        a3 = fmaf(hi_e.x, kfe.w, fmaf(hi_i.x, kfi.w, a3));
        // shift window down by 4 (index OFFS+t0-tau4-8 >= 0 always, OFFS=208)
        hi_e = lo_e; hi_i = lo_i;
        lo_e = *(const float4*)&we[OFFS + t0 - tau4 - 8];
        lo_i = *(const float4*)&wi[OFFS + t0 - tau4 - 8];
    }

    int t = tBase + t0;
    if (t     < T_DATA) g_syn[o][t]     = a0;
    if (t + 1 < T_DATA) g_syn[o][t + 1] = a1;
    if (t + 2 < T_DATA) g_syn[o][t + 2] = a2;
    if (t + 3 < T_DATA) g_syn[o][t + 3] = a3;
}

// ------------------------------------------------- dendritic tree + tanh
__global__ void tree_kernel(const float* __restrict__ W_sub, const float* __restrict__ V_o,
                            float* __restrict__ outp) {
    int t = blockIdx.x * blockDim.x + threadIdx.x;
    int var = blockIdx.y;
    if (t >= T_DATA) return;

    float ws[SUB_NO];
#pragma unroll
    for (int s = 0; s < SUB_NO; s++) ws[s] = W_sub[s];

    float so[SUB_NO];
#pragma unroll
    for (int si = SUB_NO - 1; si >= 0; si--) {
        float x = g_syn[var * 20 + si][t];
        float leaf = 0.f;
        if (2 * si + 1 < SUB_NO) leaf += so[2 * si + 1] * ws[2 * si + 1];
        if (2 * si + 2 < SUB_NO) leaf += so[2 * si + 2] * ws[2 * si + 2];
        so[si] = tanhf(x + leaf);
    }
    outp[var * T_DATA + t] = so[0] * ws[0] + V_o[0];
}

// ----------------------------------------------------------------------------
extern "C" void kernel_launch(void* const* d_in, const int* in_sizes, int n_in,
                              void* d_out, int out_size) {
    const float* Se    = (const float*)d_in[0];
    const float* Si    = (const float*)d_in[1];
    const float* u     = (const float*)d_in[2];
    const float* v     = (const float*)d_in[3];
    const float* Wsyn  = (const float*)d_in[4];
    const float* Tau   = (const float*)d_in[5];
    const float* Delta = (const float*)d_in[6];
    const float* Wsub  = (const float*)d_in[7];
    const float* Vo    = (const float*)d_in[8];
    const float* Clog  = (const float*)d_in[10];
    float* out = (float*)d_out;

    cudaFuncSetAttribute(gemm_mma, cudaFuncAttributeMaxDynamicSharedMemorySize, GEMM_SMEM);

    prep_cols<<<(NSYN * 32 + 255) / 256, 256>>>(u, v, Clog, out);
    prep_kern<<<(SUB_NO * 2 * T_NO + 255) / 256, 256>>>(Wsyn, Tau, Delta);
    gemm_mma<<<(T_DATA + 127) / 128, 256, GEMM_SMEM>>>(Se, Si);
    conv_kernel<<<dim3((T_DATA + CTT - 1) / CTT, NCH), 128>>>(Tau, Delta);
    tree_kernel<<<dim3((T_DATA + 255) / 256, 3), 256>>>(Wsub, Vo, out);
}